// round 12
// baseline (speedup 1.0000x reference)
#include <cuda_runtime.h>
#include <cuda_fp16.h>
#include <math.h>
#include <stdint.h>

// Problem constants
#define BATCH 8
#define LSEQ  2048
#define DDIM  1024
#define NEGF  (-1e30f)

// GEMM tiling: CTA 256(M) x 128(N) x 64(K halves), 16 warps as 4(m) x 4(n), warp tile 64x32
// 1 CTA per SM (512 threads, 128 regs, smem 166KB) -> same 16 warps/SM but 25% less smem write traffic
#define NTHREADS 512
#define STAGES 3
#define ROW_BYTES 144                       // 64 halves (128B) + 16B pad
#define A_ROWS 256
#define B_ROWS 128
#define A_BYTES (A_ROWS * ROW_BYTES)        // 36864
#define B_BYTES (B_ROWS * ROW_BYTES)        // 18432
#define STAGE_BYTES (A_BYTES + B_BYTES)     // 55296
#define SMEM_TOTAL (STAGES * STAGE_BYTES)   // 165888

// ---------------- scratch (device globals; no allocation allowed) ----------------
__device__ __half g_Qh [(size_t)BATCH * LSEQ * DDIM];
__device__ __half g_Kh [(size_t)BATCH * LSEQ * DDIM];
__device__ __half g_V1T[(size_t)BATCH * DDIM * LSEQ];
__device__ __half g_V2T[(size_t)BATCH * DDIM * LSEQ];
__device__ __half g_XmT[(size_t)BATCH * DDIM * LSEQ];
__device__ __half g_Eh [(size_t)BATCH * LSEQ * LSEQ];   // exp(logits) [l,m], half
__device__ __half g_ETh[(size_t)BATCH * LSEQ * LSEQ];   // exp(logits)^T [m,l], half
__device__ float  g_rowsum[BATCH * LSEQ];
__device__ float  g_colsum[BATCH * LSEQ];
__device__ __half g_x1h[(size_t)BATCH * LSEQ * DDIM];
__device__ __half g_x2h[(size_t)BATCH * LSEQ * DDIM];
__device__ __half g_Wqh[(size_t)DDIM * DDIM];
__device__ __half g_Wkh[(size_t)DDIM * DDIM];
__device__ __half g_Wvh[(size_t)DDIM * DDIM];

// ---------------- helpers ----------------
__device__ __forceinline__ uint32_t smem_to_u32(const void* p) {
    uint32_t a;
    asm("{ .reg .u64 t; cvta.to.shared.u64 t, %1; cvt.u32.u64 %0, t; }" : "=r"(a) : "l"(p));
    return a;
}

#define CP_ASYNC16(dst, src) \
    asm volatile("cp.async.cg.shared.global [%0], [%1], 16;" :: "r"(dst), "l"(src) : "memory")
#define CP_COMMIT() asm volatile("cp.async.commit_group;" ::: "memory")

#define LDSM_X4(r, addr) \
    asm volatile("ldmatrix.sync.aligned.m8n8.x4.shared.b16 {%0,%1,%2,%3}, [%4];" \
        : "=r"((r)[0]), "=r"((r)[1]), "=r"((r)[2]), "=r"((r)[3]) : "r"(addr))

// m16n8k16 fp16 MMA, fp32 accumulate
#define MMA_F16(d, a, b)                                                   \
    asm volatile(                                                          \
        "mma.sync.aligned.m16n8k16.row.col.f32.f16.f16.f32 "               \
        "{%0,%1,%2,%3}, {%4,%5,%6,%7}, {%8,%9}, {%0,%1,%2,%3};"            \
        : "+f"(d[0]), "+f"(d[1]), "+f"(d[2]), "+f"(d[3])                   \
        : "r"(a[0]), "r"(a[1]), "r"(a[2]), "r"(a[3]), "r"(b[0]), "r"(b[1]))

// ---------------------------------------------------------------------------
// NT GEMM body: C[m,n] = sum_k A[m,k]*B[n,k]; A,B __half [rows, K] k-contig.
// CTA tile 256x128x64. Warp tile 64x32 (16 warps, 4m x 4n).
// MODE 0: +bias[n], HALF out, normal store
// MODE 1: +bias[n], HALF out, transposed store C[n,m]
// MODE 2: e=__expf(acc*scale+(1-mask[z,n])*NEG); HALF dual store (normal Cv[m,n]
//         + transposed Cv2[n,m]) + atomic row/col sums
// MODE 3: FLOAT out, normal store, rows scaled by rcp(bias[z*M+m])  (bias = rowsum)
// MODE 4: HALF out, transposed store, rows scaled by mask[z,m]*rcp(bias[z*M+m]) (bias = colsum)
// ---------------------------------------------------------------------------
template <int MODE>
__device__ __forceinline__
void gemm_body(const __half* __restrict__ A, const __half* __restrict__ B,
               void* __restrict__ Cv, void* __restrict__ Cv2,
               int M, int N, int K, long long sA, long long sB, long long sC,
               const float* __restrict__ bias, const float* __restrict__ mask, float scale,
               int z, int m0, int n0, char* smc)
{
    const uint32_t smem_u = smem_to_u32(smc);
    const int tid = threadIdx.x, wid = tid >> 5, lane = tid & 31;
    const int wm = wid & 3, wn = wid >> 2;      // 4 x 4 warps, warp tile 64(m) x 32(n)
    const int g = lane >> 2, tg = lane & 3;

    const __half* Abase = A + (long long)z * sA + (long long)m0 * K;
    const __half* Bbase = B + (long long)z * sB + (long long)n0 * K;
    const int T = K >> 6;                       // 64 halves per k-tile

    // cp.async staging: 256 rows A + 128 rows B, rows of 64 halves = 128B = 8 chunks of 16B
    const int sr = tid >> 3;                    // 0..63
    const int sj = tid & 7;                     // chunk 0..7
    auto stage = [&](int u) {
        const int s = u % STAGES;
        const uint32_t sa = smem_u + s * STAGE_BYTES;
        const uint32_t sb = sa + A_BYTES;
        const __half* Asrc = Abase + (size_t)u * 64 + sj * 8;
        const __half* Bsrc = Bbase + (size_t)u * 64 + sj * 8;
        const uint32_t dw = sj * 16;
#pragma unroll
        for (int i = 0; i < 4; ++i) {
            const int r = sr + i * 64;
            CP_ASYNC16(sa + r * ROW_BYTES + dw, Asrc + (size_t)r * K);
        }
#pragma unroll
        for (int i = 0; i < 2; ++i) {
            const int r = sr + i * 64;
            CP_ASYNC16(sb + r * ROW_BYTES + dw, Bsrc + (size_t)r * K);
        }
        CP_COMMIT();
    };

    float acc[4][4][4];
#pragma unroll
    for (int a = 0; a < 4; ++a)
#pragma unroll
        for (int b = 0; b < 4; ++b)
#pragma unroll
            for (int c = 0; c < 4; ++c) acc[a][b][c] = 0.0f;

    stage(0);
    stage(1);

    // ldmatrix per-thread address offsets (bytes)
    const uint32_t a_lm = (uint32_t)((wm * 64 + (lane & 15)) * ROW_BYTES + (lane >> 4) * 16);
    const uint32_t b_lm = (uint32_t)((wn * 32 + ((lane >> 4) << 3) + (lane & 7)) * ROW_BYTES +
                                     ((lane >> 3) & 1) * 16);

    for (int t = 0; t < T; ++t) {
        if (t < T - 1) asm volatile("cp.async.wait_group 1;" ::: "memory");
        else           asm volatile("cp.async.wait_group 0;" ::: "memory");
        __syncthreads();

        if (t + 2 < T) stage(t + 2);

        const uint32_t sbase = smem_u + (t % STAGES) * STAGE_BYTES;
#pragma unroll
        for (int ks = 0; ks < 4; ++ks) {        // 4 k16 steps per 64-half tile
            const uint32_t abase = sbase + a_lm + ks * 32;
            const uint32_t bbase = sbase + A_BYTES + b_lm + ks * 32;
            uint32_t af[4][4], bf[2][4];
#pragma unroll
            for (int mt = 0; mt < 4; ++mt) LDSM_X4(af[mt], abase + mt * (16 * ROW_BYTES));
#pragma unroll
            for (int np = 0; np < 2; ++np) LDSM_X4(bf[np], bbase + np * (16 * ROW_BYTES));
#pragma unroll
            for (int mt = 0; mt < 4; ++mt)
#pragma unroll
                for (int nt = 0; nt < 4; ++nt)
                    MMA_F16(acc[mt][nt], af[mt], (bf[nt >> 1] + (nt & 1) * 2));
        }
    }

    // ---------------- epilogue ----------------
    if (MODE == 0) {
        __half* Cb = (__half*)Cv + (long long)z * sC;
#pragma unroll
        for (int mt = 0; mt < 4; ++mt)
#pragma unroll
            for (int nt = 0; nt < 4; ++nt) {
                const int mA = m0 + wm * 64 + mt * 16 + g;
                const int n  = n0 + wn * 32 + nt * 8 + tg * 2;
                const float b0 = bias[n], b1 = bias[n + 1];
                *(__half2*)(Cb + (long long)mA * N + n) =
                    __floats2half2_rn(acc[mt][nt][0] + b0, acc[mt][nt][1] + b1);
                *(__half2*)(Cb + (long long)(mA + 8) * N + n) =
                    __floats2half2_rn(acc[mt][nt][2] + b0, acc[mt][nt][3] + b1);
            }
    } else if (MODE == 2) {
        // exp in place, normal half store, atomic sums, then transposed half store
        __half* Cb  = (__half*)Cv  + (long long)z * sC;
        __half* Cb2 = (__half*)Cv2 + (long long)z * sC;
        float rs[8], cs[8];
#pragma unroll
        for (int i = 0; i < 8; ++i) { rs[i] = 0.0f; cs[i] = 0.0f; }
#pragma unroll
        for (int mt = 0; mt < 4; ++mt)
#pragma unroll
            for (int nt = 0; nt < 4; ++nt) {
                const int mA = m0 + wm * 64 + mt * 16 + g;
                const int n  = n0 + wn * 32 + nt * 8 + tg * 2;
                const float mb0 = (1.0f - mask[(long long)z * N + n]) * NEGF;
                const float mb1 = (1.0f - mask[(long long)z * N + n + 1]) * NEGF;
                const float e0 = __expf(acc[mt][nt][0] * scale + mb0);
                const float e1 = __expf(acc[mt][nt][1] * scale + mb1);
                const float e2 = __expf(acc[mt][nt][2] * scale + mb0);
                const float e3 = __expf(acc[mt][nt][3] * scale + mb1);
                acc[mt][nt][0] = e0; acc[mt][nt][1] = e1;
                acc[mt][nt][2] = e2; acc[mt][nt][3] = e3;
                *(__half2*)(Cb + (long long)mA * N + n)       = __floats2half2_rn(e0, e1);
                *(__half2*)(Cb + (long long)(mA + 8) * N + n) = __floats2half2_rn(e2, e3);
                rs[mt * 2]     += e0 + e1;
                rs[mt * 2 + 1] += e2 + e3;
                cs[nt * 2]     += e0 + e2;
                cs[nt * 2 + 1] += e1 + e3;
            }
        // row sums: reduce over tg (lane bits 0-1)
#pragma unroll
        for (int i = 0; i < 8; ++i) {
            rs[i] += __shfl_xor_sync(0xffffffffu, rs[i], 1);
            rs[i] += __shfl_xor_sync(0xffffffffu, rs[i], 2);
        }
        if (tg == 0) {
#pragma unroll
            for (int mt = 0; mt < 4; ++mt) {
                atomicAdd(&g_rowsum[z * LSEQ + m0 + wm * 64 + mt * 16 + g],     rs[mt * 2]);
                atomicAdd(&g_rowsum[z * LSEQ + m0 + wm * 64 + mt * 16 + g + 8], rs[mt * 2 + 1]);
            }
        }
        // col sums: reduce over g (lane bits 2-4)
#pragma unroll
        for (int i = 0; i < 8; ++i) {
            cs[i] += __shfl_xor_sync(0xffffffffu, cs[i], 4);
            cs[i] += __shfl_xor_sync(0xffffffffu, cs[i], 8);
            cs[i] += __shfl_xor_sync(0xffffffffu, cs[i], 16);
        }
        if (g == 0) {
#pragma unroll
            for (int nt = 0; nt < 4; ++nt) {
                atomicAdd(&g_colsum[z * LSEQ + n0 + wn * 32 + nt * 8 + tg * 2],     cs[nt * 2]);
                atomicAdd(&g_colsum[z * LSEQ + n0 + wn * 32 + nt * 8 + tg * 2 + 1], cs[nt * 2 + 1]);
            }
        }
        // transposed store of e: ET[n, m]
        {
            float* Csh = (float*)smc;   // [256][33]
#pragma unroll 1
            for (int ch = 0; ch < 4; ++ch) {
                __syncthreads();
                if (wn == ch) {
#pragma unroll
                    for (int mt = 0; mt < 4; ++mt)
#pragma unroll
                        for (int nt = 0; nt < 4; ++nt) {
                            const int ml = wm * 64 + mt * 16 + g;
                            const int nl = nt * 8 + tg * 2;
                            Csh[ml * 33 + nl]           = acc[mt][nt][0];
                            Csh[ml * 33 + nl + 1]       = acc[mt][nt][1];
                            Csh[(ml + 8) * 33 + nl]     = acc[mt][nt][2];
                            Csh[(ml + 8) * 33 + nl + 1] = acc[mt][nt][3];
                        }
                }
                __syncthreads();
#pragma unroll
                for (int i = 0; i < 16; ++i) {
                    const int idx = tid + i * NTHREADS;
                    const int nl = idx >> 8, m = idx & 255;
                    Cb2[(long long)(n0 + ch * 32 + nl) * M + m0 + m] =
                        __float2half_rn(Csh[m * 33 + nl]);
                }
            }
        }
    } else if (MODE == 3) {
        // float out, rows scaled by rcp(rowsum)
        float* Cb = (float*)Cv + (long long)z * sC;
#pragma unroll
        for (int mt = 0; mt < 4; ++mt) {
            const int mA = m0 + wm * 64 + mt * 16 + g;
            const float r0v = bias[z * M + mA];
            const float r1v = bias[z * M + mA + 8];
            const float rr0 = r0v > 0.0f ? 1.0f / r0v : 0.0f;
            const float rr1 = r1v > 0.0f ? 1.0f / r1v : 0.0f;
#pragma unroll
            for (int nt = 0; nt < 4; ++nt) {
                const int n = n0 + wn * 32 + nt * 8 + tg * 2;
                *(float2*)(Cb + (long long)mA * N + n) =
                    make_float2(acc[mt][nt][0] * rr0, acc[mt][nt][1] * rr0);
                *(float2*)(Cb + (long long)(mA + 8) * N + n) =
                    make_float2(acc[mt][nt][2] * rr1, acc[mt][nt][3] * rr1);
            }
        }
    } else {
        // MODE 1 / MODE 4: transposed HALF store via smem staging, four 32-col chunks
        float* Csh = (float*)smc;   // [256][33]
        __half* Cb = (__half*)Cv + (long long)z * sC;
#pragma unroll 1
        for (int ch = 0; ch < 4; ++ch) {
            __syncthreads();
            if (wn == ch) {
#pragma unroll
                for (int mt = 0; mt < 4; ++mt) {
                    const int ml = wm * 64 + mt * 16 + g;
                    float f0 = 1.0f, f1 = 1.0f;
                    if (MODE == 4) {
                        const float c0 = bias[z * M + m0 + ml];
                        const float c1 = bias[z * M + m0 + ml + 8];
                        f0 = mask[(long long)z * M + m0 + ml]     * (c0 > 0.0f ? 1.0f / c0 : 0.0f);
                        f1 = mask[(long long)z * M + m0 + ml + 8] * (c1 > 0.0f ? 1.0f / c1 : 0.0f);
                    }
#pragma unroll
                    for (int nt = 0; nt < 4; ++nt) {
                        const int nl = nt * 8 + tg * 2;
                        float v0 = acc[mt][nt][0], v1 = acc[mt][nt][1];
                        float v2 = acc[mt][nt][2], v3 = acc[mt][nt][3];
                        if (MODE == 1) {
                            const float b0 = bias[n0 + ch * 32 + nl];
                            const float b1 = bias[n0 + ch * 32 + nl + 1];
                            v0 += b0; v1 += b1; v2 += b0; v3 += b1;
                        }
                        if (MODE == 4) {
                            v0 *= f0; v1 *= f0; v2 *= f1; v3 *= f1;
                        }
                        Csh[ml * 33 + nl]           = v0;
                        Csh[ml * 33 + nl + 1]       = v1;
                        Csh[(ml + 8) * 33 + nl]     = v2;
                        Csh[(ml + 8) * 33 + nl + 1] = v3;
                    }
                }
            }
            __syncthreads();
#pragma unroll
            for (int i = 0; i < 16; ++i) {
                const int idx = tid + i * NTHREADS;
                const int nl = idx >> 8, m = idx & 255;
                Cb[(long long)(n0 + ch * 32 + nl) * M + m0 + m] =
                    __float2half_rn(Csh[m * 33 + nl]);
            }
        }
    }
}

// ---------------- GEMM kernel wrappers ----------------
// All projections in one launch: z<8 -> x1 {Q, V1T}; z>=8 -> x2 {K, V2T}
__global__ __launch_bounds__(NTHREADS, 1)
void proj_all_k(const __half* __restrict__ x1h, const __half* __restrict__ x2h,
                const __half* __restrict__ Wqh, const __half* __restrict__ Wkh,
                const __half* __restrict__ Wvh,
                __half* __restrict__ Qh, __half* __restrict__ Kh,
                __half* __restrict__ V1T, __half* __restrict__ V2T,
                const float* __restrict__ bq, const float* __restrict__ bk,
                const float* __restrict__ bv)
{
    extern __shared__ char smc[];
    const int zz = blockIdx.z, m0 = blockIdx.y * 256, bx = blockIdx.x;
    const long long sX = (long long)LSEQ * DDIM;
    const long long sT = (long long)DDIM * LSEQ;
    if (zz < 8) {
        if (bx < 8)
            gemm_body<0>(x1h, Wqh, Qh,  nullptr, LSEQ, DDIM, DDIM, sX, 0, sX, bq, nullptr, 0.f, zz, m0, bx * 128, smc);
        else
            gemm_body<1>(x1h, Wvh, V1T, nullptr, LSEQ, DDIM, DDIM, sX, 0, sT, bv, nullptr, 0.f, zz, m0, (bx - 8) * 128, smc);
    } else {
        const int z = zz - 8;
        if (bx < 8)
            gemm_body<0>(x2h, Wkh, Kh,  nullptr, LSEQ, DDIM, DDIM, sX, 0, sX, bk, nullptr, 0.f, z, m0, bx * 128, smc);
        else
            gemm_body<1>(x2h, Wvh, V2T, nullptr, LSEQ, DDIM, DDIM, sX, 0, sT, bv, nullptr, 0.f, z, m0, (bx - 8) * 128, smc);
    }
}

// Logits GEMM with fused exp + dual store (E, ET) + row/col sums
__global__ __launch_bounds__(NTHREADS, 1)
void sgemm_k(const __half* __restrict__ Q, const __half* __restrict__ Kh,
             __half* __restrict__ E, __half* __restrict__ ET,
             const float* __restrict__ mask, float scale)
{
    extern __shared__ char smc[];
    const long long sX = (long long)LSEQ * DDIM;
    const long long sS = (long long)LSEQ * LSEQ;
    gemm_body<2>(Q, Kh, E, ET, LSEQ, LSEQ, DDIM, sX, sX, sS, nullptr, mask, scale,
                 blockIdx.z, blockIdx.y * 256, blockIdx.x * 128, smc);
}

// merged apply: z<8: x2_out = (E @ V2) * rcp(rowsum)  |  z>=8: XmT = (ET @ V1) * mask*rcp(colsum)
__global__ __launch_bounds__(NTHREADS, 1)
void apply_dual_k(const __half* __restrict__ E, const __half* __restrict__ ET,
                  const __half* __restrict__ V2T, const __half* __restrict__ V1T,
                  float* __restrict__ out2, __half* __restrict__ XmT,
                  const float* __restrict__ rowsum, const float* __restrict__ colsum,
                  const float* __restrict__ mask)
{
    extern __shared__ char smc[];
    const int m0 = blockIdx.y * 256, n0 = blockIdx.x * 128;
    const long long sX = (long long)LSEQ * DDIM;
    const long long sT = (long long)DDIM * LSEQ;
    const long long sS = (long long)LSEQ * LSEQ;
    if (blockIdx.z < 8)
        gemm_body<3>(E, V2T, out2, nullptr, LSEQ, DDIM, LSEQ, sS, sT, sX, rowsum, nullptr, 0.f,
                     blockIdx.z, m0, n0, smc);
    else
        gemm_body<4>(ET, V1T, XmT, nullptr, LSEQ, DDIM, LSEQ, sS, sT, sT, colsum, mask, 0.f,
                     blockIdx.z - 8, m0, n0, smc);
}

// x1_out = (E @ x1_mid) * rcp(rowsum)
__global__ __launch_bounds__(NTHREADS, 1)
void final_k(const __half* __restrict__ E, const __half* __restrict__ XmT,
             float* __restrict__ out1, const float* __restrict__ rowsum)
{
    extern __shared__ char smc[];
    const long long sX = (long long)LSEQ * DDIM;
    const long long sT = (long long)DDIM * LSEQ;
    const long long sS = (long long)LSEQ * LSEQ;
    gemm_body<3>(E, XmT, out1, nullptr, LSEQ, DDIM, LSEQ, sS, sT, sX, rowsum, nullptr, 0.f,
                 blockIdx.z, blockIdx.y * 256, blockIdx.x * 128, smc);
}

// ---------------- merged fp32 -> fp16 conversion + sum zeroing ----------------
#define NX4 (BATCH * LSEQ * DDIM / 4)   // 4194304
#define NW4 (DDIM * DDIM / 4)           // 262144
#define CVT_TOTAL (2 * NX4 + 3 * NW4)   // 9175040

__global__ __launch_bounds__(256)
void cvt_all_k(const float4* __restrict__ x1, const float4* __restrict__ x2,
               const float4* __restrict__ Wq, const float4* __restrict__ Wk,
               const float4* __restrict__ Wv,
               __half2* __restrict__ x1h, __half2* __restrict__ x2h,
               __half2* __restrict__ Wqh, __half2* __restrict__ Wkh,
               __half2* __restrict__ Wvh)
{
    int i = blockIdx.x * 256 + threadIdx.x;
    if (i < BATCH * LSEQ) {
        g_rowsum[i] = 0.0f;
        g_colsum[i] = 0.0f;
    }
    if (i >= CVT_TOTAL) return;
    const float4* src;
    __half2* dst;
    if (i < NX4)               { src = x1; dst = x1h; }
    else if (i < 2 * NX4)      { src = x2; dst = x2h; i -= NX4; }
    else if (i < 2 * NX4 + NW4)     { src = Wq; dst = Wqh; i -= 2 * NX4; }
    else if (i < 2 * NX4 + 2 * NW4) { src = Wk; dst = Wkh; i -= 2 * NX4 + NW4; }
    else                            { src = Wv; dst = Wvh; i -= 2 * NX4 + 2 * NW4; }
    const float4 v = src[i];
    dst[2 * i]     = __floats2half2_rn(v.x, v.y);
    dst[2 * i + 1] = __floats2half2_rn(v.z, v.w);
}

// ---------------- launcher ----------------
extern "C" void kernel_launch(void* const* d_in, const int* in_sizes, int n_in,
                              void* d_out, int out_size)
{
    const float* x1   = (const float*)d_in[0];
    const float* x2   = (const float*)d_in[1];
    const float* mask = (const float*)d_in[2];
    const float* Wq   = (const float*)d_in[3];
    const float* bq   = (const float*)d_in[4];
    const float* Wk   = (const float*)d_in[5];
    const float* bk   = (const float*)d_in[6];
    const float* Wv   = (const float*)d_in[7];
    const float* bv   = (const float*)d_in[8];

    float* out1 = (float*)d_out;
    float* out2 = out1 + (long long)BATCH * LSEQ * DDIM;

    __half *Qh, *Kh, *V1T, *V2T, *XmT, *Eh, *ETh, *x1h, *x2h, *Wqh, *Wkh, *Wvh;
    float *rowsum, *colsum;
    cudaGetSymbolAddress((void**)&Qh,     g_Qh);
    cudaGetSymbolAddress((void**)&Kh,     g_Kh);
    cudaGetSymbolAddress((void**)&V1T,    g_V1T);
    cudaGetSymbolAddress((void**)&V2T,    g_V2T);
    cudaGetSymbolAddress((void**)&XmT,    g_XmT);
    cudaGetSymbolAddress((void**)&Eh,     g_Eh);
    cudaGetSymbolAddress((void**)&ETh,    g_ETh);
    cudaGetSymbolAddress((void**)&rowsum, g_rowsum);
    cudaGetSymbolAddress((void**)&colsum, g_colsum);
    cudaGetSymbolAddress((void**)&x1h,    g_x1h);
    cudaGetSymbolAddress((void**)&x2h,    g_x2h);
    cudaGetSymbolAddress((void**)&Wqh,    g_Wqh);
    cudaGetSymbolAddress((void**)&Wkh,    g_Wkh);
    cudaGetSymbolAddress((void**)&Wvh,    g_Wvh);

    cudaFuncSetAttribute(proj_all_k,   cudaFuncAttributeMaxDynamicSharedMemorySize, SMEM_TOTAL);
    cudaFuncSetAttribute(sgemm_k,      cudaFuncAttributeMaxDynamicSharedMemorySize, SMEM_TOTAL);
    cudaFuncSetAttribute(apply_dual_k, cudaFuncAttributeMaxDynamicSharedMemorySize, SMEM_TOTAL);
    cudaFuncSetAttribute(final_k,      cudaFuncAttributeMaxDynamicSharedMemorySize, SMEM_TOTAL);

    const float scale = 0.03125f;  // 1/sqrt(1024)

    dim3 blk(NTHREADS);

    // convert all external inputs to fp16 + zero sums (single launch)
    cvt_all_k<<<(CVT_TOTAL + 255) / 256, 256>>>((const float4*)x1, (const float4*)x2,
                                                (const float4*)Wq, (const float4*)Wk,
                                                (const float4*)Wv,
                                                (__half2*)x1h, (__half2*)x2h,
                                                (__half2*)Wqh, (__half2*)Wkh, (__half2*)Wvh);

    // all projections: x1 -> {Q, V1T}; x2 -> {K, V2T}
    proj_all_k<<<dim3(16, 8, 16), blk, SMEM_TOTAL>>>(x1h, x2h, Wqh, Wkh, Wvh,
                                                     Qh, Kh, V1T, V2T, bq, bk, bv);

    // logits GEMM: E = exp(QK^T*scale + maskbias), dual store (E, ET) + row/col sums
    sgemm_k<<<dim3(16, 8, 8), blk, SMEM_TOTAL>>>(Qh, Kh, Eh, ETh, mask, scale);

    // merged apply: x2_out = (E@V2)/rowsum  |  XmT = (ET@V1)*mask/colsum
    apply_dual_k<<<dim3(8, 8, 16), blk, SMEM_TOTAL>>>(Eh, ETh, V2T, V1T, out2, XmT,
                                                      rowsum, colsum, mask);

    // x1_out = (E @ x1_mid)/rowsum
    final_k<<<dim3(8, 8, 8), blk, SMEM_TOTAL>>>(Eh, XmT, out1, rowsum);
}

// round 13
// speedup vs baseline: 1.0930x; 1.0930x over previous
#include <cuda_runtime.h>
#include <cuda_fp16.h>
#include <math.h>
#include <stdint.h>

// Problem constants
#define BATCH 8
#define LSEQ  2048
#define DDIM  1024
#define NEGF  (-1e30f)

// GEMM tiling: CTA 128(M) x 128(N) x 64(K halves), 8 warps as 2(m) x 4(n), warp tile 64x32
// 2 CTAs per SM (regs capped to 128, smem 110.6KB/CTA) — independent barrier domains hide k-tile syncs
#define NTHREADS 256
#define STAGES 3
#define ROW_BYTES 144                       // 64 halves (128B) + 16B pad
#define A_BYTES (128 * ROW_BYTES)           // 18432
#define B_BYTES (128 * ROW_BYTES)           // 18432
#define STAGE_BYTES (A_BYTES + B_BYTES)     // 36864
#define SMEM_TOTAL (STAGES * STAGE_BYTES)   // 110592

// ---------------- scratch (device globals; no allocation allowed) ----------------
__device__ __half g_Qh [(size_t)BATCH * LSEQ * DDIM];
__device__ __half g_Kh [(size_t)BATCH * LSEQ * DDIM];
__device__ __half g_V1T[(size_t)BATCH * DDIM * LSEQ];
__device__ __half g_V2T[(size_t)BATCH * DDIM * LSEQ];
__device__ __half g_XmT[(size_t)BATCH * DDIM * LSEQ];
__device__ __half g_Eh [(size_t)BATCH * LSEQ * LSEQ];   // exp(logits) [l,m], half
__device__ __half g_ETh[(size_t)BATCH * LSEQ * LSEQ];   // exp(logits)^T [m,l], half
__device__ float  g_rowsum[BATCH * LSEQ];
__device__ float  g_colsum[BATCH * LSEQ];
__device__ __half g_x1h[(size_t)BATCH * LSEQ * DDIM];
__device__ __half g_x2h[(size_t)BATCH * LSEQ * DDIM];
__device__ __half g_Wqh[(size_t)DDIM * DDIM];
__device__ __half g_Wkh[(size_t)DDIM * DDIM];
__device__ __half g_Wvh[(size_t)DDIM * DDIM];

// ---------------- helpers ----------------
__device__ __forceinline__ uint32_t smem_to_u32(const void* p) {
    uint32_t a;
    asm("{ .reg .u64 t; cvta.to.shared.u64 t, %1; cvt.u32.u64 %0, t; }" : "=r"(a) : "l"(p));
    return a;
}

#define CP_ASYNC16(dst, src) \
    asm volatile("cp.async.cg.shared.global [%0], [%1], 16;" :: "r"(dst), "l"(src) : "memory")
#define CP_COMMIT() asm volatile("cp.async.commit_group;" ::: "memory")

#define LDSM_X4(r, addr) \
    asm volatile("ldmatrix.sync.aligned.m8n8.x4.shared.b16 {%0,%1,%2,%3}, [%4];" \
        : "=r"((r)[0]), "=r"((r)[1]), "=r"((r)[2]), "=r"((r)[3]) : "r"(addr))

// m16n8k16 fp16 MMA, fp32 accumulate
#define MMA_F16(d, a, b)                                                   \
    asm volatile(                                                          \
        "mma.sync.aligned.m16n8k16.row.col.f32.f16.f16.f32 "               \
        "{%0,%1,%2,%3}, {%4,%5,%6,%7}, {%8,%9}, {%0,%1,%2,%3};"            \
        : "+f"(d[0]), "+f"(d[1]), "+f"(d[2]), "+f"(d[3])                   \
        : "r"(a[0]), "r"(a[1]), "r"(a[2]), "r"(a[3]), "r"(b[0]), "r"(b[1]))

// ---------------------------------------------------------------------------
// NT GEMM body: C[m,n] = sum_k A[m,k]*B[n,k]; A,B __half [rows, K] k-contig.
// CTA tile 128x128x64. Warp tile 64x32.
// MODE 0: +bias[n], HALF out, normal store
// MODE 1: +bias[n], HALF out, transposed store C[n,m]
// MODE 2: e=__expf(acc*scale+(1-mask[z,n])*NEG); HALF dual store (normal Cv[m,n]
//         + transposed Cv2[n,m]) + atomic row/col sums
// MODE 3: FLOAT out, normal store, rows scaled by rcp(bias[z*M+m])  (bias = rowsum)
// MODE 4: HALF out, transposed store, rows scaled by mask[z,m]*rcp(bias[z*M+m]) (bias = colsum)
// ---------------------------------------------------------------------------
template <int MODE>
__device__ __forceinline__
void gemm_body(const __half* __restrict__ A, const __half* __restrict__ B,
               void* __restrict__ Cv, void* __restrict__ Cv2,
               int M, int N, int K, long long sA, long long sB, long long sC,
               const float* __restrict__ bias, const float* __restrict__ mask, float scale,
               int z, int m0, int n0, char* smc)
{
    const uint32_t smem_u = smem_to_u32(smc);
    const int tid = threadIdx.x, wid = tid >> 5, lane = tid & 31;
    const int wm = wid & 1, wn = wid >> 1;      // 2 x 4 warps, warp tile 64(m) x 32(n)
    const int g = lane >> 2, tg = lane & 3;

    const __half* Abase = A + (long long)z * sA + (long long)m0 * K;
    const __half* Bbase = B + (long long)z * sB + (long long)n0 * K;
    const int T = K >> 6;                       // 64 halves per k-tile

    // cp.async staging: 128 rows A + 128 rows B, rows of 64 halves = 128B = 8 chunks of 16B
    const int sr = tid >> 3;                    // 0..31
    const int sj = tid & 7;                     // chunk 0..7
    auto stage = [&](int u) {
        const int s = u % STAGES;
        const uint32_t sa = smem_u + s * STAGE_BYTES;
        const uint32_t sb = sa + A_BYTES;
        const __half* Asrc = Abase + (size_t)u * 64 + sj * 8;
        const __half* Bsrc = Bbase + (size_t)u * 64 + sj * 8;
        const uint32_t dw = sj * 16;
#pragma unroll
        for (int i = 0; i < 4; ++i) {
            const int r = sr + i * 32;
            CP_ASYNC16(sa + r * ROW_BYTES + dw, Asrc + (size_t)r * K);
        }
#pragma unroll
        for (int i = 0; i < 4; ++i) {
            const int r = sr + i * 32;
            CP_ASYNC16(sb + r * ROW_BYTES + dw, Bsrc + (size_t)r * K);
        }
        CP_COMMIT();
    };

    float acc[4][4][4];
#pragma unroll
    for (int a = 0; a < 4; ++a)
#pragma unroll
        for (int b = 0; b < 4; ++b)
#pragma unroll
            for (int c = 0; c < 4; ++c) acc[a][b][c] = 0.0f;

    stage(0);
    stage(1);

    // ldmatrix per-thread address offsets (bytes)
    const uint32_t a_lm = (uint32_t)((wm * 64 + (lane & 15)) * ROW_BYTES + (lane >> 4) * 16);
    const uint32_t b_lm = (uint32_t)((wn * 32 + ((lane >> 4) << 3) + (lane & 7)) * ROW_BYTES +
                                     ((lane >> 3) & 1) * 16);

    for (int t = 0; t < T; ++t) {
        if (t < T - 1) asm volatile("cp.async.wait_group 1;" ::: "memory");
        else           asm volatile("cp.async.wait_group 0;" ::: "memory");
        __syncthreads();

        const uint32_t sbase = smem_u + (t % STAGES) * STAGE_BYTES;

        // load ks=0 fragments FIRST so MMAs can start before cp.async issue burst
        uint32_t af[4][4], bf[2][4];
#pragma unroll
        for (int mt = 0; mt < 4; ++mt) LDSM_X4(af[mt], sbase + a_lm + mt * (16 * ROW_BYTES));
#pragma unroll
        for (int np = 0; np < 2; ++np) LDSM_X4(bf[np], sbase + A_BYTES + b_lm + np * (16 * ROW_BYTES));

        if (t + 2 < T) stage(t + 2);

#pragma unroll
        for (int ks = 0; ks < 4; ++ks) {        // 4 k16 steps per 64-half tile
#pragma unroll
            for (int mt = 0; mt < 4; ++mt)
#pragma unroll
                for (int nt = 0; nt < 4; ++nt)
                    MMA_F16(acc[mt][nt], af[mt], (bf[nt >> 1] + (nt & 1) * 2));
            if (ks < 3) {
                const uint32_t abase = sbase + a_lm + (ks + 1) * 32;
                const uint32_t bbase = sbase + A_BYTES + b_lm + (ks + 1) * 32;
#pragma unroll
                for (int mt = 0; mt < 4; ++mt) LDSM_X4(af[mt], abase + mt * (16 * ROW_BYTES));
#pragma unroll
                for (int np = 0; np < 2; ++np) LDSM_X4(bf[np], bbase + np * (16 * ROW_BYTES));
            }
        }
    }

    // ---------------- epilogue ----------------
    if (MODE == 0) {
        __half* Cb = (__half*)Cv + (long long)z * sC;
#pragma unroll
        for (int mt = 0; mt < 4; ++mt)
#pragma unroll
            for (int nt = 0; nt < 4; ++nt) {
                const int mA = m0 + wm * 64 + mt * 16 + g;
                const int n  = n0 + wn * 32 + nt * 8 + tg * 2;
                const float b0 = bias[n], b1 = bias[n + 1];
                *(__half2*)(Cb + (long long)mA * N + n) =
                    __floats2half2_rn(acc[mt][nt][0] + b0, acc[mt][nt][1] + b1);
                *(__half2*)(Cb + (long long)(mA + 8) * N + n) =
                    __floats2half2_rn(acc[mt][nt][2] + b0, acc[mt][nt][3] + b1);
            }
    } else if (MODE == 2) {
        // exp in place, normal half store, atomic sums, then transposed half store
        __half* Cb  = (__half*)Cv  + (long long)z * sC;
        __half* Cb2 = (__half*)Cv2 + (long long)z * sC;
        float rs[8], cs[8];
#pragma unroll
        for (int i = 0; i < 8; ++i) { rs[i] = 0.0f; cs[i] = 0.0f; }
#pragma unroll
        for (int mt = 0; mt < 4; ++mt)
#pragma unroll
            for (int nt = 0; nt < 4; ++nt) {
                const int mA = m0 + wm * 64 + mt * 16 + g;
                const int n  = n0 + wn * 32 + nt * 8 + tg * 2;
                const float mb0 = (1.0f - mask[(long long)z * N + n]) * NEGF;
                const float mb1 = (1.0f - mask[(long long)z * N + n + 1]) * NEGF;
                const float e0 = __expf(acc[mt][nt][0] * scale + mb0);
                const float e1 = __expf(acc[mt][nt][1] * scale + mb1);
                const float e2 = __expf(acc[mt][nt][2] * scale + mb0);
                const float e3 = __expf(acc[mt][nt][3] * scale + mb1);
                acc[mt][nt][0] = e0; acc[mt][nt][1] = e1;
                acc[mt][nt][2] = e2; acc[mt][nt][3] = e3;
                *(__half2*)(Cb + (long long)mA * N + n)       = __floats2half2_rn(e0, e1);
                *(__half2*)(Cb + (long long)(mA + 8) * N + n) = __floats2half2_rn(e2, e3);
                rs[mt * 2]     += e0 + e1;
                rs[mt * 2 + 1] += e2 + e3;
                cs[nt * 2]     += e0 + e2;
                cs[nt * 2 + 1] += e1 + e3;
            }
        // row sums: reduce over tg (lane bits 0-1)
#pragma unroll
        for (int i = 0; i < 8; ++i) {
            rs[i] += __shfl_xor_sync(0xffffffffu, rs[i], 1);
            rs[i] += __shfl_xor_sync(0xffffffffu, rs[i], 2);
        }
        if (tg == 0) {
#pragma unroll
            for (int mt = 0; mt < 4; ++mt) {
                atomicAdd(&g_rowsum[z * LSEQ + m0 + wm * 64 + mt * 16 + g],     rs[mt * 2]);
                atomicAdd(&g_rowsum[z * LSEQ + m0 + wm * 64 + mt * 16 + g + 8], rs[mt * 2 + 1]);
            }
        }
        // col sums: reduce over g (lane bits 2-4)
#pragma unroll
        for (int i = 0; i < 8; ++i) {
            cs[i] += __shfl_xor_sync(0xffffffffu, cs[i], 4);
            cs[i] += __shfl_xor_sync(0xffffffffu, cs[i], 8);
            cs[i] += __shfl_xor_sync(0xffffffffu, cs[i], 16);
        }
        if (g == 0) {
#pragma unroll
            for (int nt = 0; nt < 4; ++nt) {
                atomicAdd(&g_colsum[z * LSEQ + n0 + wn * 32 + nt * 8 + tg * 2],     cs[nt * 2]);
                atomicAdd(&g_colsum[z * LSEQ + n0 + wn * 32 + nt * 8 + tg * 2 + 1], cs[nt * 2 + 1]);
            }
        }
        // transposed store of e: ET[n, m]
        {
            float* Csh = (float*)smc;   // [128][33]
#pragma unroll 1
            for (int ch = 0; ch < 4; ++ch) {
                __syncthreads();
                if (wn == ch) {
#pragma unroll
                    for (int mt = 0; mt < 4; ++mt)
#pragma unroll
                        for (int nt = 0; nt < 4; ++nt) {
                            const int ml = wm * 64 + mt * 16 + g;
                            const int nl = nt * 8 + tg * 2;
                            Csh[ml * 33 + nl]           = acc[mt][nt][0];
                            Csh[ml * 33 + nl + 1]       = acc[mt][nt][1];
                            Csh[(ml + 8) * 33 + nl]     = acc[mt][nt][2];
                            Csh[(ml + 8) * 33 + nl + 1] = acc[mt][nt][3];
                        }
                }
                __syncthreads();
#pragma unroll
                for (int i = 0; i < 16; ++i) {
                    const int idx = tid + i * 256;
                    const int nl = idx >> 7, m = idx & 127;
                    Cb2[(long long)(n0 + ch * 32 + nl) * M + m0 + m] =
                        __float2half_rn(Csh[m * 33 + nl]);
                }
            }
        }
    } else if (MODE == 3) {
        // float out, rows scaled by rcp(rowsum)
        float* Cb = (float*)Cv + (long long)z * sC;
#pragma unroll
        for (int mt = 0; mt < 4; ++mt) {
            const int mA = m0 + wm * 64 + mt * 16 + g;
            const float r0v = bias[z * M + mA];
            const float r1v = bias[z * M + mA + 8];
            const float rr0 = r0v > 0.0f ? 1.0f / r0v : 0.0f;
            const float rr1 = r1v > 0.0f ? 1.0f / r1v : 0.0f;
#pragma unroll
            for (int nt = 0; nt < 4; ++nt) {
                const int n = n0 + wn * 32 + nt * 8 + tg * 2;
                *(float2*)(Cb + (long long)mA * N + n) =
                    make_float2(acc[mt][nt][0] * rr0, acc[mt][nt][1] * rr0);
                *(float2*)(Cb + (long long)(mA + 8) * N + n) =
                    make_float2(acc[mt][nt][2] * rr1, acc[mt][nt][3] * rr1);
            }
        }
    } else {
        // MODE 1 / MODE 4: transposed HALF store via smem staging, four 32-col chunks
        float* Csh = (float*)smc;   // [128][33]
        __half* Cb = (__half*)Cv + (long long)z * sC;
#pragma unroll 1
        for (int ch = 0; ch < 4; ++ch) {
            __syncthreads();
            if (wn == ch) {
#pragma unroll
                for (int mt = 0; mt < 4; ++mt) {
                    const int ml = wm * 64 + mt * 16 + g;
                    float f0 = 1.0f, f1 = 1.0f;
                    if (MODE == 4) {
                        const float c0 = bias[z * M + m0 + ml];
                        const float c1 = bias[z * M + m0 + ml + 8];
                        f0 = mask[(long long)z * M + m0 + ml]     * (c0 > 0.0f ? 1.0f / c0 : 0.0f);
                        f1 = mask[(long long)z * M + m0 + ml + 8] * (c1 > 0.0f ? 1.0f / c1 : 0.0f);
                    }
#pragma unroll
                    for (int nt = 0; nt < 4; ++nt) {
                        const int nl = nt * 8 + tg * 2;
                        float v0 = acc[mt][nt][0], v1 = acc[mt][nt][1];
                        float v2 = acc[mt][nt][2], v3 = acc[mt][nt][3];
                        if (MODE == 1) {
                            const float b0 = bias[n0 + ch * 32 + nl];
                            const float b1 = bias[n0 + ch * 32 + nl + 1];
                            v0 += b0; v1 += b1; v2 += b0; v3 += b1;
                        }
                        if (MODE == 4) {
                            v0 *= f0; v1 *= f0; v2 *= f1; v3 *= f1;
                        }
                        Csh[ml * 33 + nl]           = v0;
                        Csh[ml * 33 + nl + 1]       = v1;
                        Csh[(ml + 8) * 33 + nl]     = v2;
                        Csh[(ml + 8) * 33 + nl + 1] = v3;
                    }
                }
            }
            __syncthreads();
#pragma unroll
            for (int i = 0; i < 16; ++i) {
                const int idx = tid + i * 256;
                const int nl = idx >> 7, m = idx & 127;
                Cb[(long long)(n0 + ch * 32 + nl) * M + m0 + m] =
                    __float2half_rn(Csh[m * 33 + nl]);
            }
        }
    }
}

// ---------------- GEMM kernel wrappers ----------------
// All projections in one launch: z<8 -> x1 {Q, V1T}; z>=8 -> x2 {K, V2T}
__global__ __launch_bounds__(NTHREADS, 2)
void proj_all_k(const __half* __restrict__ x1h, const __half* __restrict__ x2h,
                const __half* __restrict__ Wqh, const __half* __restrict__ Wkh,
                const __half* __restrict__ Wvh,
                __half* __restrict__ Qh, __half* __restrict__ Kh,
                __half* __restrict__ V1T, __half* __restrict__ V2T,
                const float* __restrict__ bq, const float* __restrict__ bk,
                const float* __restrict__ bv)
{
    extern __shared__ char smc[];
    const int zz = blockIdx.z, m0 = blockIdx.y * 128, bx = blockIdx.x;
    const long long sX = (long long)LSEQ * DDIM;
    const long long sT = (long long)DDIM * LSEQ;
    if (zz < 8) {
        if (bx < 8)
            gemm_body<0>(x1h, Wqh, Qh,  nullptr, LSEQ, DDIM, DDIM, sX, 0, sX, bq, nullptr, 0.f, zz, m0, bx * 128, smc);
        else
            gemm_body<1>(x1h, Wvh, V1T, nullptr, LSEQ, DDIM, DDIM, sX, 0, sT, bv, nullptr, 0.f, zz, m0, (bx - 8) * 128, smc);
    } else {
        const int z = zz - 8;
        if (bx < 8)
            gemm_body<0>(x2h, Wkh, Kh,  nullptr, LSEQ, DDIM, DDIM, sX, 0, sX, bk, nullptr, 0.f, z, m0, bx * 128, smc);
        else
            gemm_body<1>(x2h, Wvh, V2T, nullptr, LSEQ, DDIM, DDIM, sX, 0, sT, bv, nullptr, 0.f, z, m0, (bx - 8) * 128, smc);
    }
}

// Logits GEMM with fused exp + dual store (E, ET) + row/col sums
__global__ __launch_bounds__(NTHREADS, 2)
void sgemm_k(const __half* __restrict__ Q, const __half* __restrict__ Kh,
             __half* __restrict__ E, __half* __restrict__ ET,
             const float* __restrict__ mask, float scale)
{
    extern __shared__ char smc[];
    const long long sX = (long long)LSEQ * DDIM;
    const long long sS = (long long)LSEQ * LSEQ;
    gemm_body<2>(Q, Kh, E, ET, LSEQ, LSEQ, DDIM, sX, sX, sS, nullptr, mask, scale,
                 blockIdx.z, blockIdx.y * 128, blockIdx.x * 128, smc);
}

// merged apply: z<8: x2_out = (E @ V2) * rcp(rowsum)  |  z>=8: XmT = (ET @ V1) * mask*rcp(colsum)
__global__ __launch_bounds__(NTHREADS, 2)
void apply_dual_k(const __half* __restrict__ E, const __half* __restrict__ ET,
                  const __half* __restrict__ V2T, const __half* __restrict__ V1T,
                  float* __restrict__ out2, __half* __restrict__ XmT,
                  const float* __restrict__ rowsum, const float* __restrict__ colsum,
                  const float* __restrict__ mask)
{
    extern __shared__ char smc[];
    const int m0 = blockIdx.y * 128, n0 = blockIdx.x * 128;
    const long long sX = (long long)LSEQ * DDIM;
    const long long sT = (long long)DDIM * LSEQ;
    const long long sS = (long long)LSEQ * LSEQ;
    if (blockIdx.z < 8)
        gemm_body<3>(E, V2T, out2, nullptr, LSEQ, DDIM, LSEQ, sS, sT, sX, rowsum, nullptr, 0.f,
                     blockIdx.z, m0, n0, smc);
    else
        gemm_body<4>(ET, V1T, XmT, nullptr, LSEQ, DDIM, LSEQ, sS, sT, sT, colsum, mask, 0.f,
                     blockIdx.z - 8, m0, n0, smc);
}

// x1_out = (E @ x1_mid) * rcp(rowsum)
__global__ __launch_bounds__(NTHREADS, 2)
void final_k(const __half* __restrict__ E, const __half* __restrict__ XmT,
             float* __restrict__ out1, const float* __restrict__ rowsum)
{
    extern __shared__ char smc[];
    const long long sX = (long long)LSEQ * DDIM;
    const long long sT = (long long)DDIM * LSEQ;
    const long long sS = (long long)LSEQ * LSEQ;
    gemm_body<3>(E, XmT, out1, nullptr, LSEQ, DDIM, LSEQ, sS, sT, sX, rowsum, nullptr, 0.f,
                 blockIdx.z, blockIdx.y * 128, blockIdx.x * 128, smc);
}

// ---------------- merged fp32 -> fp16 conversion + sum zeroing ----------------
#define NX4 (BATCH * LSEQ * DDIM / 4)   // 4194304
#define NW4 (DDIM * DDIM / 4)           // 262144
#define CVT_TOTAL (2 * NX4 + 3 * NW4)   // 9175040

__global__ __launch_bounds__(256)
void cvt_all_k(const float4* __restrict__ x1, const float4* __restrict__ x2,
               const float4* __restrict__ Wq, const float4* __restrict__ Wk,
               const float4* __restrict__ Wv,
               __half2* __restrict__ x1h, __half2* __restrict__ x2h,
               __half2* __restrict__ Wqh, __half2* __restrict__ Wkh,
               __half2* __restrict__ Wvh)
{
    int i = blockIdx.x * 256 + threadIdx.x;
    if (i < BATCH * LSEQ) {
        g_rowsum[i] = 0.0f;
        g_colsum[i] = 0.0f;
    }
    if (i >= CVT_TOTAL) return;
    const float4* src;
    __half2* dst;
    if (i < NX4)               { src = x1; dst = x1h; }
    else if (i < 2 * NX4)      { src = x2; dst = x2h; i -= NX4; }
    else if (i < 2 * NX4 + NW4)     { src = Wq; dst = Wqh; i -= 2 * NX4; }
    else if (i < 2 * NX4 + 2 * NW4) { src = Wk; dst = Wkh; i -= 2 * NX4 + NW4; }
    else                            { src = Wv; dst = Wvh; i -= 2 * NX4 + 2 * NW4; }
    const float4 v = src[i];
    dst[2 * i]     = __floats2half2_rn(v.x, v.y);
    dst[2 * i + 1] = __floats2half2_rn(v.z, v.w);
}

// ---------------- launcher ----------------
extern "C" void kernel_launch(void* const* d_in, const int* in_sizes, int n_in,
                              void* d_out, int out_size)
{
    const float* x1   = (const float*)d_in[0];
    const float* x2   = (const float*)d_in[1];
    const float* mask = (const float*)d_in[2];
    const float* Wq   = (const float*)d_in[3];
    const float* bq   = (const float*)d_in[4];
    const float* Wk   = (const float*)d_in[5];
    const float* bk   = (const float*)d_in[6];
    const float* Wv   = (const float*)d_in[7];
    const float* bv   = (const float*)d_in[8];

    float* out1 = (float*)d_out;
    float* out2 = out1 + (long long)BATCH * LSEQ * DDIM;

    __half *Qh, *Kh, *V1T, *V2T, *XmT, *Eh, *ETh, *x1h, *x2h, *Wqh, *Wkh, *Wvh;
    float *rowsum, *colsum;
    cudaGetSymbolAddress((void**)&Qh,     g_Qh);
    cudaGetSymbolAddress((void**)&Kh,     g_Kh);
    cudaGetSymbolAddress((void**)&V1T,    g_V1T);
    cudaGetSymbolAddress((void**)&V2T,    g_V2T);
    cudaGetSymbolAddress((void**)&XmT,    g_XmT);
    cudaGetSymbolAddress((void**)&Eh,     g_Eh);
    cudaGetSymbolAddress((void**)&ETh,    g_ETh);
    cudaGetSymbolAddress((void**)&rowsum, g_rowsum);
    cudaGetSymbolAddress((void**)&colsum, g_colsum);
    cudaGetSymbolAddress((void**)&x1h,    g_x1h);
    cudaGetSymbolAddress((void**)&x2h,    g_x2h);
    cudaGetSymbolAddress((void**)&Wqh,    g_Wqh);
    cudaGetSymbolAddress((void**)&Wkh,    g_Wkh);
    cudaGetSymbolAddress((void**)&Wvh,    g_Wvh);

    cudaFuncSetAttribute(proj_all_k,   cudaFuncAttributeMaxDynamicSharedMemorySize, SMEM_TOTAL);
    cudaFuncSetAttribute(sgemm_k,      cudaFuncAttributeMaxDynamicSharedMemorySize, SMEM_TOTAL);
    cudaFuncSetAttribute(apply_dual_k, cudaFuncAttributeMaxDynamicSharedMemorySize, SMEM_TOTAL);
    cudaFuncSetAttribute(final_k,      cudaFuncAttributeMaxDynamicSharedMemorySize, SMEM_TOTAL);

    const float scale = 0.03125f;  // 1/sqrt(1024)

    dim3 blk(NTHREADS);

    // convert all external inputs to fp16 + zero sums (single launch)
    cvt_all_k<<<(CVT_TOTAL + 255) / 256, 256>>>((const float4*)x1, (const float4*)x2,
                                                (const float4*)Wq, (const float4*)Wk,
                                                (const float4*)Wv,
                                                (__half2*)x1h, (__half2*)x2h,
                                                (__half2*)Wqh, (__half2*)Wkh, (__half2*)Wvh);

    // all projections: x1 -> {Q, V1T}; x2 -> {K, V2T}
    proj_all_k<<<dim3(16, 16, 16), blk, SMEM_TOTAL>>>(x1h, x2h, Wqh, Wkh, Wvh,
                                                      Qh, Kh, V1T, V2T, bq, bk, bv);

    // logits GEMM: E = exp(QK^T*scale + maskbias), dual store (E, ET) + row/col sums
    sgemm_k<<<dim3(16, 16, 8), blk, SMEM_TOTAL>>>(Qh, Kh, Eh, ETh, mask, scale);

    // merged apply: x2_out = (E@V2)/rowsum  |  XmT = (ET@V1)*mask/colsum
    apply_dual_k<<<dim3(8, 16, 16), blk, SMEM_TOTAL>>>(Eh, ETh, V2T, V1T, out2, XmT,
                                                       rowsum, colsum, mask);

    // x1_out = (E @ x1_mid)/rowsum
    final_k<<<dim3(8, 16, 8), blk, SMEM_TOTAL>>>(Eh, XmT, out1, rowsum);
}

// round 15
// speedup vs baseline: 1.1254x; 1.0296x over previous
#include <cuda_runtime.h>
#include <cuda_fp16.h>
#include <math.h>
#include <stdint.h>

// Problem constants
#define BATCH 8
#define LSEQ  2048
#define DDIM  1024
#define NEGF  (-1e30f)

// GEMM tiling: CTA 128(M) x 128(N) x 64(K halves), 8 warps as 2(m) x 4(n), warp tile 64x32
// 2 CTAs per SM (regs capped to 128, smem 110.6KB/CTA) — independent barrier domains hide k-tile syncs
#define NTHREADS 256
#define STAGES 3
#define ROW_BYTES 144                       // 64 halves (128B) + 16B pad
#define A_BYTES (128 * ROW_BYTES)           // 18432
#define B_BYTES (128 * ROW_BYTES)           // 18432
#define STAGE_BYTES (A_BYTES + B_BYTES)     // 36864
#define SMEM_TOTAL (STAGES * STAGE_BYTES)   // 110592
#define TSTRIDE 136                         // transposed-epilogue smem stride (halves)

// ---------------- scratch (device globals; no allocation allowed) ----------------
__device__ __half g_Qh [(size_t)BATCH * LSEQ * DDIM];
__device__ __half g_Kh [(size_t)BATCH * LSEQ * DDIM];
__device__ __half g_V1T[(size_t)BATCH * DDIM * LSEQ];
__device__ __half g_V2T[(size_t)BATCH * DDIM * LSEQ];
__device__ __half g_XmT[(size_t)BATCH * DDIM * LSEQ];
__device__ __half g_Eh [(size_t)BATCH * LSEQ * LSEQ];   // exp(logits) [l,m], half
__device__ __half g_ETh[(size_t)BATCH * LSEQ * LSEQ];   // exp(logits)^T [m,l], half
__device__ float  g_rowsum[BATCH * LSEQ];
__device__ float  g_colsum[BATCH * LSEQ];
__device__ __half g_x1h[(size_t)BATCH * LSEQ * DDIM];
__device__ __half g_x2h[(size_t)BATCH * LSEQ * DDIM];
__device__ __half g_Wqh[(size_t)DDIM * DDIM];
__device__ __half g_Wkh[(size_t)DDIM * DDIM];
__device__ __half g_Wvh[(size_t)DDIM * DDIM];

// ---------------- helpers ----------------
__device__ __forceinline__ uint32_t smem_to_u32(const void* p) {
    uint32_t a;
    asm("{ .reg .u64 t; cvta.to.shared.u64 t, %1; cvt.u32.u64 %0, t; }" : "=r"(a) : "l"(p));
    return a;
}

#define CP_ASYNC16(dst, src) \
    asm volatile("cp.async.cg.shared.global [%0], [%1], 16;" :: "r"(dst), "l"(src) : "memory")
#define CP_COMMIT() asm volatile("cp.async.commit_group;" ::: "memory")

#define LDSM_X4(r, addr) \
    asm volatile("ldmatrix.sync.aligned.m8n8.x4.shared.b16 {%0,%1,%2,%3}, [%4];" \
        : "=r"((r)[0]), "=r"((r)[1]), "=r"((r)[2]), "=r"((r)[3]) : "r"(addr))

// m16n8k16 fp16 MMA, fp32 accumulate
#define MMA_F16(d, a, b)                                                   \
    asm volatile(                                                          \
        "mma.sync.aligned.m16n8k16.row.col.f32.f16.f16.f32 "               \
        "{%0,%1,%2,%3}, {%4,%5,%6,%7}, {%8,%9}, {%0,%1,%2,%3};"            \
        : "+f"(d[0]), "+f"(d[1]), "+f"(d[2]), "+f"(d[3])                   \
        : "r"(a[0]), "r"(a[1]), "r"(a[2]), "r"(a[3]), "r"(b[0]), "r"(b[1]))

// ---------------------------------------------------------------------------
// NT GEMM body: C[m,n] = sum_k A[m,k]*B[n,k]; A,B __half [rows, KV] k-contig.
// KV compile-time. CTA tile 128x128x64. Warp tile 64x32.
// MODE 0: +bias[n], HALF out, normal store
// MODE 1: +bias[n], HALF out, transposed store C[n,m]
// MODE 2: e=__expf(acc*scale+(1-mask[z,n])*NEG); HALF dual store (normal Cv[m,n]
//         + transposed Cv2[n,m]) + atomic row/col sums
// MODE 3: FLOAT out, normal store, rows scaled by rcp(bias[z*M+m])  (bias = rowsum)
// MODE 4: HALF out, transposed store, rows scaled by mask[z,m]*rcp(bias[z*M+m]) (bias = colsum)
// ---------------------------------------------------------------------------
template <int MODE, int KV>
__device__ __forceinline__
void gemm_body(const __half* __restrict__ A, const __half* __restrict__ B,
               void* __restrict__ Cv, void* __restrict__ Cv2,
               int M, int N, long long sA, long long sB, long long sC,
               const float* __restrict__ bias, const float* __restrict__ mask, float scale,
               int z, int m0, int n0, char* smc)
{
    const uint32_t smem_u = smem_to_u32(smc);
    const int tid = threadIdx.x, wid = tid >> 5, lane = tid & 31;
    const int wm = wid & 1, wn = wid >> 1;      // 2 x 4 warps, warp tile 64(m) x 32(n)
    const int g = lane >> 2, tg = lane & 3;

    const __half* Abase = A + (long long)z * sA + (long long)m0 * KV;
    const __half* Bbase = B + (long long)z * sB + (long long)n0 * KV;
    constexpr int T = KV >> 6;                  // 64 halves per k-tile

    // cp.async staging: 128 rows A + 128 rows B, rows of 64 halves = 128B = 8 chunks of 16B
    const int sr = tid >> 3;                    // 0..31
    const int sj = tid & 7;                     // chunk 0..7
    auto stage = [&](int u) {
        const int s = u % STAGES;
        const uint32_t sa = smem_u + s * STAGE_BYTES;
        const uint32_t sb = sa + A_BYTES;
        const __half* Asrc = Abase + (size_t)u * 64 + sj * 8;
        const __half* Bsrc = Bbase + (size_t)u * 64 + sj * 8;
        const uint32_t dw = sj * 16;
#pragma unroll
        for (int i = 0; i < 4; ++i) {
            const int r = sr + i * 32;
            CP_ASYNC16(sa + r * ROW_BYTES + dw, Asrc + (size_t)r * KV);
        }
#pragma unroll
        for (int i = 0; i < 4; ++i) {
            const int r = sr + i * 32;
            CP_ASYNC16(sb + r * ROW_BYTES + dw, Bsrc + (size_t)r * KV);
        }
        CP_COMMIT();
    };

    float acc[4][4][4];
#pragma unroll
    for (int a = 0; a < 4; ++a)
#pragma unroll
        for (int b = 0; b < 4; ++b)
#pragma unroll
            for (int c = 0; c < 4; ++c) acc[a][b][c] = 0.0f;

    stage(0);
    stage(1);

    // ldmatrix per-thread address offsets (bytes)
    const uint32_t a_lm = (uint32_t)((wm * 64 + (lane & 15)) * ROW_BYTES + (lane >> 4) * 16);
    const uint32_t b_lm = (uint32_t)((wn * 32 + ((lane >> 4) << 3) + (lane & 7)) * ROW_BYTES +
                                     ((lane >> 3) & 1) * 16);

#pragma unroll 3
    for (int t = 0; t < T; ++t) {
        if (t < T - 1) asm volatile("cp.async.wait_group 1;" ::: "memory");
        else           asm volatile("cp.async.wait_group 0;" ::: "memory");
        __syncthreads();

        const uint32_t sbase = smem_u + (t % STAGES) * STAGE_BYTES;

        // load ks=0 fragments FIRST so MMAs can start before cp.async issue burst
        uint32_t af[4][4], bf[2][4];
#pragma unroll
        for (int mt = 0; mt < 4; ++mt) LDSM_X4(af[mt], sbase + a_lm + mt * (16 * ROW_BYTES));
#pragma unroll
        for (int np = 0; np < 2; ++np) LDSM_X4(bf[np], sbase + A_BYTES + b_lm + np * (16 * ROW_BYTES));

        if (t + 2 < T) stage(t + 2);

#pragma unroll
        for (int ks = 0; ks < 4; ++ks) {        // 4 k16 steps per 64-half tile
#pragma unroll
            for (int mt = 0; mt < 4; ++mt)
#pragma unroll
                for (int nt = 0; nt < 4; ++nt)
                    MMA_F16(acc[mt][nt], af[mt], (bf[nt >> 1] + (nt & 1) * 2));
            if (ks < 3) {
                const uint32_t abase = sbase + a_lm + (ks + 1) * 32;
                const uint32_t bbase = sbase + A_BYTES + b_lm + (ks + 1) * 32;
#pragma unroll
                for (int mt = 0; mt < 4; ++mt) LDSM_X4(af[mt], abase + mt * (16 * ROW_BYTES));
#pragma unroll
                for (int np = 0; np < 2; ++np) LDSM_X4(bf[np], bbase + np * (16 * ROW_BYTES));
            }
        }
    }

    // ---------------- epilogue ----------------
    const int ml0 = wm * 64;                    // warp m-origin within tile
    const int nl0 = wn * 32 + tg * 2;           // thread n-origin within tile

    if (MODE == 0) {
        __half* Cb = (__half*)Cv + (long long)z * sC;
#pragma unroll
        for (int mt = 0; mt < 4; ++mt)
#pragma unroll
            for (int nt = 0; nt < 4; ++nt) {
                const int mA = m0 + ml0 + mt * 16 + g;
                const int n  = n0 + nl0 + nt * 8;
                const float b0 = bias[n], b1 = bias[n + 1];
                *(__half2*)(Cb + (long long)mA * N + n) =
                    __floats2half2_rn(acc[mt][nt][0] + b0, acc[mt][nt][1] + b1);
                *(__half2*)(Cb + (long long)(mA + 8) * N + n) =
                    __floats2half2_rn(acc[mt][nt][2] + b0, acc[mt][nt][3] + b1);
            }
    } else if (MODE == 3) {
        // float out, rows scaled by rcp(rowsum)
        float* Cb = (float*)Cv + (long long)z * sC;
#pragma unroll
        for (int mt = 0; mt < 4; ++mt) {
            const int mA = m0 + ml0 + mt * 16 + g;
            const float r0v = bias[z * M + mA];
            const float r1v = bias[z * M + mA + 8];
            const float rr0 = r0v > 0.0f ? 1.0f / r0v : 0.0f;
            const float rr1 = r1v > 0.0f ? 1.0f / r1v : 0.0f;
#pragma unroll
            for (int nt = 0; nt < 4; ++nt) {
                const int n = n0 + nl0 + nt * 8;
                *(float2*)(Cb + (long long)mA * N + n) =
                    make_float2(acc[mt][nt][0] * rr0, acc[mt][nt][1] * rr0);
                *(float2*)(Cb + (long long)(mA + 8) * N + n) =
                    make_float2(acc[mt][nt][2] * rr1, acc[mt][nt][3] * rr1);
            }
        }
    } else {
        // MODE 1 / 2 / 4: transposed half store via one smem staging pass.
        // MODE 2 additionally does normal half store + atomic row/col sums first.
        __half* Esh = (__half*)smc;             // [128 n][TSTRIDE m] halves, 34.8KB

        if (MODE == 2) {
            __half* Cb = (__half*)Cv + (long long)z * sC;
            float rs[8], cs[8];
#pragma unroll
            for (int i = 0; i < 8; ++i) { rs[i] = 0.0f; cs[i] = 0.0f; }
#pragma unroll
            for (int mt = 0; mt < 4; ++mt)
#pragma unroll
                for (int nt = 0; nt < 4; ++nt) {
                    const int mA = m0 + ml0 + mt * 16 + g;
                    const int n  = n0 + nl0 + nt * 8;
                    const float mb0 = (1.0f - mask[(long long)z * N + n]) * NEGF;
                    const float mb1 = (1.0f - mask[(long long)z * N + n + 1]) * NEGF;
                    const float e0 = __expf(acc[mt][nt][0] * scale + mb0);
                    const float e1 = __expf(acc[mt][nt][1] * scale + mb1);
                    const float e2 = __expf(acc[mt][nt][2] * scale + mb0);
                    const float e3 = __expf(acc[mt][nt][3] * scale + mb1);
                    acc[mt][nt][0] = e0; acc[mt][nt][1] = e1;
                    acc[mt][nt][2] = e2; acc[mt][nt][3] = e3;
                    *(__half2*)(Cb + (long long)mA * N + n)       = __floats2half2_rn(e0, e1);
                    *(__half2*)(Cb + (long long)(mA + 8) * N + n) = __floats2half2_rn(e2, e3);
                    rs[mt * 2]     += e0 + e1;
                    rs[mt * 2 + 1] += e2 + e3;
                    cs[nt * 2]     += e0 + e2;
                    cs[nt * 2 + 1] += e1 + e3;
                }
#pragma unroll
            for (int i = 0; i < 8; ++i) {
                rs[i] += __shfl_xor_sync(0xffffffffu, rs[i], 1);
                rs[i] += __shfl_xor_sync(0xffffffffu, rs[i], 2);
            }
            if (tg == 0) {
#pragma unroll
                for (int mt = 0; mt < 4; ++mt) {
                    atomicAdd(&g_rowsum[z * LSEQ + m0 + ml0 + mt * 16 + g],     rs[mt * 2]);
                    atomicAdd(&g_rowsum[z * LSEQ + m0 + ml0 + mt * 16 + g + 8], rs[mt * 2 + 1]);
                }
            }
#pragma unroll
            for (int i = 0; i < 8; ++i) {
                cs[i] += __shfl_xor_sync(0xffffffffu, cs[i], 4);
                cs[i] += __shfl_xor_sync(0xffffffffu, cs[i], 8);
                cs[i] += __shfl_xor_sync(0xffffffffu, cs[i], 16);
            }
            if (g == 0) {
#pragma unroll
                for (int nt = 0; nt < 4; ++nt) {
                    atomicAdd(&g_colsum[z * LSEQ + n0 + nl0 + nt * 8],     cs[nt * 2]);
                    atomicAdd(&g_colsum[z * LSEQ + n0 + nl0 + nt * 8 + 1], cs[nt * 2 + 1]);
                }
            }
        }

        __syncthreads();                        // all warps done reading stage smem
#pragma unroll
        for (int mt = 0; mt < 4; ++mt) {
            const int ml = ml0 + mt * 16 + g;
            float f0 = 1.0f, f1 = 1.0f;
            if (MODE == 4) {
                const float c0 = bias[z * M + m0 + ml];
                const float c1 = bias[z * M + m0 + ml + 8];
                f0 = mask[(long long)z * M + m0 + ml]     * (c0 > 0.0f ? 1.0f / c0 : 0.0f);
                f1 = mask[(long long)z * M + m0 + ml + 8] * (c1 > 0.0f ? 1.0f / c1 : 0.0f);
            }
#pragma unroll
            for (int nt = 0; nt < 4; ++nt) {
                const int nl = nl0 + nt * 8;
                float v0 = acc[mt][nt][0], v1 = acc[mt][nt][1];
                float v2 = acc[mt][nt][2], v3 = acc[mt][nt][3];
                if (MODE == 1) {
                    const float b0 = bias[n0 + nl];
                    const float b1 = bias[n0 + nl + 1];
                    v0 += b0; v1 += b1; v2 += b0; v3 += b1;
                }
                if (MODE == 4) {
                    v0 *= f0; v1 *= f0; v2 *= f1; v3 *= f1;
                }
                Esh[nl * TSTRIDE + ml]           = __float2half_rn(v0);
                Esh[(nl + 1) * TSTRIDE + ml]     = __float2half_rn(v1);
                Esh[nl * TSTRIDE + ml + 8]       = __float2half_rn(v2);
                Esh[(nl + 1) * TSTRIDE + ml + 8] = __float2half_rn(v3);
            }
        }
        __syncthreads();
        __half* Cb2 = (__half*)((MODE == 2) ? Cv2 : Cv) + (long long)z * sC;
#pragma unroll
        for (int i = 0; i < 32; ++i) {
            const int idx = tid + i * 256;
            const int nl = idx >> 6;            // 0..127
            const int mp = idx & 63;            // half2 index within column
            *(__half2*)(Cb2 + (long long)(n0 + nl) * M + m0 + mp * 2) =
                *(const __half2*)(Esh + nl * TSTRIDE + mp * 2);
        }
    }
}

// ---------------- GEMM kernel wrappers ----------------
// All projections in one launch: z<8 -> x1 {Q, V1T}; z>=8 -> x2 {K, V2T}
__global__ __launch_bounds__(NTHREADS, 2)
void proj_all_k(const __half* __restrict__ x1h, const __half* __restrict__ x2h,
                const __half* __restrict__ Wqh, const __half* __restrict__ Wkh,
                const __half* __restrict__ Wvh,
                __half* __restrict__ Qh, __half* __restrict__ Kh,
                __half* __restrict__ V1T, __half* __restrict__ V2T,
                const float* __restrict__ bq, const float* __restrict__ bk,
                const float* __restrict__ bv)
{
    extern __shared__ char smc[];
    const int zz = blockIdx.z, m0 = blockIdx.y * 128, bx = blockIdx.x;
    const long long sX = (long long)LSEQ * DDIM;
    const long long sT = (long long)DDIM * LSEQ;
    if (zz < 8) {
        if (bx < 8)
            gemm_body<0, DDIM>(x1h, Wqh, Qh,  nullptr, LSEQ, DDIM, sX, 0, sX, bq, nullptr, 0.f, zz, m0, bx * 128, smc);
        else
            gemm_body<1, DDIM>(x1h, Wvh, V1T, nullptr, LSEQ, DDIM, sX, 0, sT, bv, nullptr, 0.f, zz, m0, (bx - 8) * 128, smc);
    } else {
        const int z = zz - 8;
        if (bx < 8)
            gemm_body<0, DDIM>(x2h, Wkh, Kh,  nullptr, LSEQ, DDIM, sX, 0, sX, bk, nullptr, 0.f, z, m0, bx * 128, smc);
        else
            gemm_body<1, DDIM>(x2h, Wvh, V2T, nullptr, LSEQ, DDIM, sX, 0, sT, bv, nullptr, 0.f, z, m0, (bx - 8) * 128, smc);
    }
}

// Logits GEMM with fused exp + dual store (E, ET) + row/col sums
__global__ __launch_bounds__(NTHREADS, 2)
void sgemm_k(const __half* __restrict__ Q, const __half* __restrict__ Kh,
             __half* __restrict__ E, __half* __restrict__ ET,
             const float* __restrict__ mask, float scale)
{
    extern __shared__ char smc[];
    const long long sX = (long long)LSEQ * DDIM;
    const long long sS = (long long)LSEQ * LSEQ;
    gemm_body<2, DDIM>(Q, Kh, E, ET, LSEQ, LSEQ, sX, sX, sS, nullptr, mask, scale,
                       blockIdx.z, blockIdx.y * 128, blockIdx.x * 128, smc);
}

// merged apply: z<8: x2_out = (E @ V2) * rcp(rowsum)  |  z>=8: XmT = (ET @ V1) * mask*rcp(colsum)
__global__ __launch_bounds__(NTHREADS, 2)
void apply_dual_k(const __half* __restrict__ E, const __half* __restrict__ ET,
                  const __half* __restrict__ V2T, const __half* __restrict__ V1T,
                  float* __restrict__ out2, __half* __restrict__ XmT,
                  const float* __restrict__ rowsum, const float* __restrict__ colsum,
                  const float* __restrict__ mask)
{
    extern __shared__ char smc[];
    const int m0 = blockIdx.y * 128, n0 = blockIdx.x * 128;
    const long long sX = (long long)LSEQ * DDIM;
    const long long sT = (long long)DDIM * LSEQ;
    const long long sS = (long long)LSEQ * LSEQ;
    if (blockIdx.z < 8)
        gemm_body<3, LSEQ>(E, V2T, out2, nullptr, LSEQ, DDIM, sS, sT, sX, rowsum, nullptr, 0.f,
                           blockIdx.z, m0, n0, smc);
    else
        gemm_body<4, LSEQ>(ET, V1T, XmT, nullptr, LSEQ, DDIM, sS, sT, sT, colsum, mask, 0.f,
                           blockIdx.z - 8, m0, n0, smc);
}

// x1_out = (E @ x1_mid) * rcp(rowsum)
__global__ __launch_bounds__(NTHREADS, 2)
void final_k(const __half* __restrict__ E, const __half* __restrict__ XmT,
             float* __restrict__ out1, const float* __restrict__ rowsum)
{
    extern __shared__ char smc[];
    const long long sX = (long long)LSEQ * DDIM;
    const long long sT = (long long)DDIM * LSEQ;
    const long long sS = (long long)LSEQ * LSEQ;
    gemm_body<3, LSEQ>(E, XmT, out1, nullptr, LSEQ, DDIM, sS, sT, sX, rowsum, nullptr, 0.f,
                       blockIdx.z, blockIdx.y * 128, blockIdx.x * 128, smc);
}

// ---------------- merged fp32 -> fp16 conversion + sum zeroing ----------------
#define NX4 (BATCH * LSEQ * DDIM / 4)   // 4194304
#define NW4 (DDIM * DDIM / 4)           // 262144
#define CVT_TOTAL (2 * NX4 + 3 * NW4)   // 9175040

__global__ __launch_bounds__(256)
void cvt_all_k(const float4* __restrict__ x1, const float4* __restrict__ x2,
               const float4* __restrict__ Wq, const float4* __restrict__ Wk,
               const float4* __restrict__ Wv,
               __half2* __restrict__ x1h, __half2* __restrict__ x2h,
               __half2* __restrict__ Wqh, __half2* __restrict__ Wkh,
               __half2* __restrict__ Wvh)
{
    int i = blockIdx.x * 256 + threadIdx.x;
    if (i < BATCH * LSEQ) {
        g_rowsum[i] = 0.0f;
        g_colsum[i] = 0.0f;
    }
    if (i >= CVT_TOTAL) return;
    const float4* src;
    __half2* dst;
    if (i < NX4)               { src = x1; dst = x1h; }
    else if (i < 2 * NX4)      { src = x2; dst = x2h; i -= NX4; }
    else if (i < 2 * NX4 + NW4)     { src = Wq; dst = Wqh; i -= 2 * NX4; }
    else if (i < 2 * NX4 + 2 * NW4) { src = Wk; dst = Wkh; i -= 2 * NX4 + NW4; }
    else                            { src = Wv; dst = Wvh; i -= 2 * NX4 + 2 * NW4; }
    const float4 v = src[i];
    dst[2 * i]     = __floats2half2_rn(v.x, v.y);
    dst[2 * i + 1] = __floats2half2_rn(v.z, v.w);
}

// ---------------- launcher ----------------
extern "C" void kernel_launch(void* const* d_in, const int* in_sizes, int n_in,
                              void* d_out, int out_size)
{
    const float* x1   = (const float*)d_in[0];
    const float* x2   = (const float*)d_in[1];
    const float* mask = (const float*)d_in[2];
    const float* Wq   = (const float*)d_in[3];
    const float* bq   = (const float*)d_in[4];
    const float* Wk   = (const float*)d_in[5];
    const float* bk   = (const float*)d_in[6];
    const float* Wv   = (const float*)d_in[7];
    const float* bv   = (const float*)d_in[8];

    float* out1 = (float*)d_out;
    float* out2 = out1 + (long long)BATCH * LSEQ * DDIM;

    __half *Qh, *Kh, *V1T, *V2T, *XmT, *Eh, *ETh, *x1h, *x2h, *Wqh, *Wkh, *Wvh;
    float *rowsum, *colsum;
    cudaGetSymbolAddress((void**)&Qh,     g_Qh);
    cudaGetSymbolAddress((void**)&Kh,     g_Kh);
    cudaGetSymbolAddress((void**)&V1T,    g_V1T);
    cudaGetSymbolAddress((void**)&V2T,    g_V2T);
    cudaGetSymbolAddress((void**)&XmT,    g_XmT);
    cudaGetSymbolAddress((void**)&Eh,     g_Eh);
    cudaGetSymbolAddress((void**)&ETh,    g_ETh);
    cudaGetSymbolAddress((void**)&rowsum, g_rowsum);
    cudaGetSymbolAddress((void**)&colsum, g_colsum);
    cudaGetSymbolAddress((void**)&x1h,    g_x1h);
    cudaGetSymbolAddress((void**)&x2h,    g_x2h);
    cudaGetSymbolAddress((void**)&Wqh,    g_Wqh);
    cudaGetSymbolAddress((void**)&Wkh,    g_Wkh);
    cudaGetSymbolAddress((void**)&Wvh,    g_Wvh);

    cudaFuncSetAttribute(proj_all_k,   cudaFuncAttributeMaxDynamicSharedMemorySize, SMEM_TOTAL);
    cudaFuncSetAttribute(sgemm_k,      cudaFuncAttributeMaxDynamicSharedMemorySize, SMEM_TOTAL);
    cudaFuncSetAttribute(apply_dual_k, cudaFuncAttributeMaxDynamicSharedMemorySize, SMEM_TOTAL);
    cudaFuncSetAttribute(final_k,      cudaFuncAttributeMaxDynamicSharedMemorySize, SMEM_TOTAL);

    const float scale = 0.03125f;  // 1/sqrt(1024)

    dim3 blk(NTHREADS);

    // convert all external inputs to fp16 + zero sums (single launch)
    cvt_all_k<<<(CVT_TOTAL + 255) / 256, 256>>>((const float4*)x1, (const float4*)x2,
                                                (const float4*)Wq, (const float4*)Wk,
                                                (const float4*)Wv,
                                                (__half2*)x1h, (__half2*)x2h,
                                                (__half2*)Wqh, (__half2*)Wkh, (__half2*)Wvh);

    // all projections: x1 -> {Q, V1T}; x2 -> {K, V2T}
    proj_all_k<<<dim3(16, 16, 16), blk, SMEM_TOTAL>>>(x1h, x2h, Wqh, Wkh, Wvh,
                                                      Qh, Kh, V1T, V2T, bq, bk, bv);

    // logits GEMM: E = exp(QK^T*scale + maskbias), dual store (E, ET) + row/col sums
    sgemm_k<<<dim3(16, 16, 8), blk, SMEM_TOTAL>>>(Qh, Kh, Eh, ETh, mask, scale);

    // merged apply: x2_out = (E@V2)/rowsum  |  XmT = (ET@V1)*mask/colsum
    apply_dual_k<<<dim3(8, 16, 16), blk, SMEM_TOTAL>>>(Eh, ETh, V2T, V1T, out2, XmT,
                                                       rowsum, colsum, mask);

    // x1_out = (E @ x1_mid)/rowsum
    final_k<<<dim3(8, 16, 8), blk, SMEM_TOTAL>>>(Eh, XmT, out1, rowsum);
}